// round 10
// baseline (speedup 1.0000x reference)
#include <cuda_runtime.h>
#include <cuda_bf16.h>

// Problem: x [64,224,224,32] f32; W_cls [32,4]; b_cls [4].
// out[b] = rot90(x[b], k[b]) with k[b] = argmax(mean_hw(x[b]) @ W + b).
//
// Persistent fused kernel, atomic work queue (128 groups of 49 tasks),
// reduce/rotate interleaved with D=6 batch delay, grid 1184 (8/SM), last
// exiting block self-resets queue state for graph replay.
// R10 change: rotation is SCATTER (linear reads, affine-scattered writes)
// instead of gather. Reads stream perfectly; scattered stores are posted
// and drained by LTS. Inverse rotation coeffs = forward coeffs of (4-k)&3.

#define BATCH 64
#define HW    224
#define PIX   (HW * HW)        // 50176
#define CH    32
#define NCHUNK 49
#define DLY   6
#define TOTAL_TASKS (2 * BATCH * NCHUNK)      // 6272
#define GRID_BLOCKS (148 * 8)                 // 1184

// Queue state: zero-init at load, restored by last exiting block.
__device__ float4   g_partial[BATCH * NCHUNK * 8];
__device__ int      g_k[BATCH];
__device__ unsigned g_ctr;
__device__ int      g_done[BATCH];
__device__ int      g_flag[BATCH];
__device__ unsigned g_exit;

// Affine coefficients (float4 units, before +q) for offset as a function of
// (row r, col c) of the ITERATED image:
//   off(r,c) = A*r + B*c + C
// Used as: gather coeffs for rot k, or scatter (dst) coeffs for rot (4-k)&3.
//   idx0: (r,c)          idx1: (c, 223-r)
//   idx2: (223-r,223-c)  idx3: (223-c, r)
__constant__ int c_A[4] = { HW*8,      -8,      -HW*8,   8      };
__constant__ int c_B[4] = { 8,          HW*8,   -8,      -HW*8  };
__constant__ int c_C[4] = { 0,          223*8,  (223*HW+223)*8, 223*HW*8 };

__global__ void __launch_bounds__(256, 8) fused_kernel(const float4* __restrict__ x,
                                                       const float*  __restrict__ W_cls,
                                                       const float*  __restrict__ b_cls,
                                                       float4*       __restrict__ out) {
    __shared__ float4 sm[8][8];
    __shared__ float  meanv[CH];
    __shared__ int    sh_task;
    __shared__ int    sh_last;
    __shared__ int    sh_k;

    const int t    = threadIdx.x;
    const int lane = t & 31;
    const int warp = t >> 5;
    const int q    = t & 7;

    for (;;) {
        __syncthreads();
        if (t == 0) sh_task = (int)atomicAdd(&g_ctr, 1u);
        __syncthreads();
        const int task = sh_task;
        if (task >= TOTAL_TASKS) break;

        // -------- decode interleaved schedule (delay = DLY batches) --------
        const int g     = task / NCHUNK;
        const int slice = task - g * NCHUNK;
        int is_reduce, b;
        if (g < DLY)             { is_reduce = 1; b = g; }
        else if (g < 128 - DLY)  { int h = g - DLY;
                                   is_reduce = !(h & 1);
                                   b = is_reduce ? (DLY + (h >> 1)) : (h >> 1); }
        else                     { is_reduce = 0; b = (64 - DLY) + (g - (128 - DLY)); }

        if (is_reduce) {
            // ---------------- reduction chunk (order-identical to R1) -------
            const unsigned base = ((unsigned)b * PIX + (unsigned)slice * 1024u) * 8u;

            float4 s = make_float4(0.f, 0.f, 0.f, 0.f);
#pragma unroll 4
            for (int it = 0; it < 32; ++it) {
                unsigned pix = (unsigned)(it * 32 + (t >> 3));
                float4 v = __ldg(&x[base + pix * 8u + q]);
                s.x += v.x; s.y += v.y; s.z += v.z; s.w += v.w;
            }
#pragma unroll
            for (int off = 8; off <= 16; off <<= 1) {
                s.x += __shfl_xor_sync(0xffffffffu, s.x, off);
                s.y += __shfl_xor_sync(0xffffffffu, s.y, off);
                s.z += __shfl_xor_sync(0xffffffffu, s.z, off);
                s.w += __shfl_xor_sync(0xffffffffu, s.w, off);
            }
            if (lane < 8) sm[warp][lane] = s;
            __syncthreads();

            if (t < 8) {
                float4 acc = sm[0][t];
#pragma unroll
                for (int w = 1; w < 8; ++w) {
                    float4 v = sm[w][t];
                    acc.x += v.x; acc.y += v.y; acc.z += v.z; acc.w += v.w;
                }
                g_partial[(b * NCHUNK + slice) * 8 + t] = acc;
                __threadfence();
            }
            __syncthreads();

            if (t == 0) {
                int old = atomicAdd(&g_done[b], 1);
                sh_last = (old == NCHUNK - 1);
            }
            __syncthreads();

            if (sh_last) {
                if (t == 0) __threadfence();
                __syncthreads();
                if (t < CH) {
                    const int qq = t >> 2, r = t & 3;
                    float ssum = 0.f;
                    for (int ch = 0; ch < NCHUNK; ++ch) {
                        float4 v = g_partial[(b * NCHUNK + ch) * 8 + qq];
                        ssum += (r == 0) ? v.x : (r == 1) ? v.y : (r == 2) ? v.z : v.w;
                    }
                    meanv[t] = ssum * (1.0f / (float)PIX);
                }
                __syncthreads();
                if (t == 0) {
                    float best = -3.402823466e38f;
                    int bi = 0;
#pragma unroll
                    for (int o = 0; o < 4; ++o) {
                        float l = __ldg(&b_cls[o]);
#pragma unroll
                        for (int cc = 0; cc < CH; ++cc)
                            l += meanv[cc] * __ldg(&W_cls[cc * 4 + o]);
                        if (l > best) { best = l; bi = o; }  // first-max (jnp.argmax)
                    }
                    g_k[b] = bi;
                    __threadfence();
                    atomicExch(&g_flag[b], 1);
                }
            }
        } else {
            // --------- rotation slice: LINEAR reads, SCATTERED writes ------
            if (t == 0) {
                while (0 == *(volatile int*)&g_flag[b]) __nanosleep(100);
                __threadfence();
                sh_k = g_k[b];
            }
            __syncthreads();
            const int k  = sh_k;
            const int kk = (4 - k) & 3;        // dst offset coeffs = inverse rot
            const int A = c_A[kk], Bc = c_B[kk];

            const float4* src_base = x   + (unsigned)b * PIX * 8u;
            float4*       out_base = out + (unsigned)b * PIX * 8u;

            int pix0 = slice * 1024 + (t >> 3);      // source pixel (linear)
            int si = pix0 / HW;
            int sj = pix0 - si * HW;
            int doff = A * si + Bc * sj + c_C[kk] + q;  // dst float4 offset
            int soff = pix0 * 8 + q;                    // src float4 offset
            const int stepB   = 32 * Bc;
            const int wrapAdj = A - HW * Bc;

#pragma unroll 8
            for (int it = 0; it < 32; ++it) {
                float4 v = __ldg(&src_base[soff]);   // perfectly linear stream
                __stcs(&out_base[doff], v);          // posted scattered store
                soff += 32 * 8;
                sj += 32; doff += stepB;
                if (sj >= HW) { sj -= HW; doff += wrapAdj; }
            }
        }
    }

    // ---- self-reset for next graph replay: last block out cleans up ------
    __syncthreads();
    if (t == 0) {
        unsigned me = atomicAdd(&g_exit, 1u);
        if (me == GRID_BLOCKS - 1) {
            for (int i = 0; i < BATCH; ++i) { g_done[i] = 0; g_flag[i] = 0; }
            g_ctr  = 0u;
            g_exit = 0u;
            __threadfence();
        }
    }
}

extern "C" void kernel_launch(void* const* d_in, const int* in_sizes, int n_in,
                              void* d_out, int out_size) {
    const float4* x     = (const float4*)d_in[0];
    const float*  W_cls = (const float*)d_in[1];
    const float*  b_cls = (const float*)d_in[2];
    float4*       out   = (float4*)d_out;

    fused_kernel<<<GRID_BLOCKS, 256>>>(x, W_cls, b_cls, out);
}